// round 5
// baseline (speedup 1.0000x reference)
#include <cuda_runtime.h>
#include <cuda_bf16.h>
#include <cstdint>

// HalfKP NNUE forward, fully fused, 4 positions per block.
// Inputs (metadata order):
//  0 white_indices int32 [B*BAG]   1 white_offsets int64 [B] (unused)
//  2 black_indices int32 [B*BAG]   3 black_offsets int64 [B] (unused)
//  4 ft_white f32 [NUM_EMB,256]    5 ft_black f32 [NUM_EMB,256]
//  6 fc1_w f32 [32,512]  7 fc1_b [32]
//  8 fc2_w f32 [32,32]   9 fc2_b [32]
// 10 fc3_w f32 [1,32]   11 fc3_b [1]
// output f32 [B]

#define H1 256
#define P  4            // positions per block
#define MAXBAG 64

__global__ __launch_bounds__(256, 8)
void nnue_fused_kernel(const int* __restrict__ wi,
                       const int* __restrict__ bi,
                       const float* __restrict__ ftw,
                       const float* __restrict__ ftb,
                       const float* __restrict__ fc1w,
                       const float* __restrict__ fc1b,
                       const float* __restrict__ fc2w,
                       const float* __restrict__ fc2b,
                       const float* __restrict__ fc3w,
                       const float* __restrict__ fc3b,
                       float* __restrict__ out,
                       int bag, int B)
{
    const int t = threadIdx.x;               // 0..255
    const int pos0 = blockIdx.x * P;

    __shared__ int   sW[P][MAXBAG];
    __shared__ int   sB[P][MAXBAG];
    __shared__ float x[P][2 * H1];           // concat(reluW, reluB) per position
    __shared__ float h1[P][32];

    // ---- load indices (P*bag per table) ----
    for (int i = t; i < P * bag; i += 256) {
        const int p = i / bag, k = i - p * bag;
        const size_t g = (size_t)(pos0 + p) * bag + k;
        sW[p][k] = wi[g];
        sB[p][k] = bi[g];
    }
    __syncthreads();

    // ---- gather: 64 threads per position; each thread owns float4 column c4
    //      of BOTH tables (full 30-row sums, no cross-thread reduction) ----
    {
        const int p  = t >> 6;               // 0..3
        const int c4 = t & 63;               // 0..63
        const float* tw = ftw + (size_t)c4 * 4;
        const float* tb = ftb + (size_t)c4 * 4;

        float4 aw = make_float4(0.f, 0.f, 0.f, 0.f);
        float4 ab = make_float4(0.f, 0.f, 0.f, 0.f);
        #pragma unroll 5
        for (int k = 0; k < bag; k++) {
            const float4 vw = *reinterpret_cast<const float4*>(tw + (size_t)sW[p][k] * H1);
            const float4 vb = *reinterpret_cast<const float4*>(tb + (size_t)sB[p][k] * H1);
            aw.x += vw.x; aw.y += vw.y; aw.z += vw.z; aw.w += vw.w;
            ab.x += vb.x; ab.y += vb.y; ab.z += vb.z; ab.w += vb.w;
        }
        float4* xw = reinterpret_cast<float4*>(&x[p][0]) + c4;
        float4* xb = reinterpret_cast<float4*>(&x[p][H1]) + c4;
        *xw = make_float4(fmaxf(aw.x, 0.f), fmaxf(aw.y, 0.f),
                          fmaxf(aw.z, 0.f), fmaxf(aw.w, 0.f));
        *xb = make_float4(fmaxf(ab.x, 0.f), fmaxf(ab.y, 0.f),
                          fmaxf(ab.z, 0.f), fmaxf(ab.w, 0.f));
    }
    __syncthreads();

    // ---- fc1: 64 threads. lane8 = k-slice, og = group of 4 outputs.
    //      Each thread: 4 outputs x 4 positions, weights read ONCE per block. ----
    if (t < 64) {
        const int lane8 = t & 7;             // 0..7 (k-lane)
        const int og    = t >> 3;            // 0..7 -> outputs 4*og..4*og+3
        const float4* w4 = reinterpret_cast<const float4*>(fc1w);

        float acc[P][4];
        #pragma unroll
        for (int p = 0; p < P; p++)
            #pragma unroll
            for (int o = 0; o < 4; o++) acc[p][o] = 0.f;

        #pragma unroll
        for (int j = 0; j < 16; j++) {
            const int k = j * 8 + lane8;     // float4 index 0..127 (conflict-free)
            float4 w0 = w4[(og * 4 + 0) * 128 + k];
            float4 w1 = w4[(og * 4 + 1) * 128 + k];
            float4 w2 = w4[(og * 4 + 2) * 128 + k];
            float4 w3 = w4[(og * 4 + 3) * 128 + k];
            #pragma unroll
            for (int p = 0; p < P; p++) {
                const float4 xv = reinterpret_cast<const float4*>(&x[p][0])[k];
                acc[p][0] += xv.x * w0.x + xv.y * w0.y + xv.z * w0.z + xv.w * w0.w;
                acc[p][1] += xv.x * w1.x + xv.y * w1.y + xv.z * w1.z + xv.w * w1.w;
                acc[p][2] += xv.x * w2.x + xv.y * w2.y + xv.z * w2.z + xv.w * w2.w;
                acc[p][3] += xv.x * w3.x + xv.y * w3.y + xv.z * w3.z + xv.w * w3.w;
            }
        }
        // reduce across the 8 k-lanes (8-lane subsections of the warp)
        #pragma unroll
        for (int p = 0; p < P; p++)
            #pragma unroll
            for (int o = 0; o < 4; o++) {
                float s = acc[p][o];
                s += __shfl_down_sync(0xffffffffu, s, 4, 8);
                s += __shfl_down_sync(0xffffffffu, s, 2, 8);
                s += __shfl_down_sync(0xffffffffu, s, 1, 8);
                if (lane8 == 0)
                    h1[p][og * 4 + o] = fmaxf(s + fc1b[og * 4 + o], 0.f);
            }
    }
    __syncthreads();

    // ---- fc2 + fc3: 128 threads (one warp per position) ----
    if (t < 32 * P) {
        const int p = t >> 5;
        const int o = t & 31;
        float s2 = 0.f;
        #pragma unroll
        for (int k = 0; k < 32; k++) s2 += h1[p][k] * fc2w[o * 32 + k];
        const float h2 = fmaxf(s2 + fc2b[o], 0.f);
        float v = h2 * fc3w[o];
        #pragma unroll
        for (int off = 16; off > 0; off >>= 1)
            v += __shfl_down_sync(0xffffffffu, v, off);
        if (o == 0 && pos0 + p < B) out[pos0 + p] = v + fc3b[0];
    }
}

extern "C" void kernel_launch(void* const* d_in, const int* in_sizes, int n_in,
                              void* d_out, int out_size)
{
    const int*   wi   = (const int*)  d_in[0];
    const int*   bi   = (const int*)  d_in[2];
    const float* ftw  = (const float*)d_in[4];
    const float* ftb  = (const float*)d_in[5];
    const float* fc1w = (const float*)d_in[6];
    const float* fc1b = (const float*)d_in[7];
    const float* fc2w = (const float*)d_in[8];
    const float* fc2b = (const float*)d_in[9];
    const float* fc3w = (const float*)d_in[10];
    const float* fc3b = (const float*)d_in[11];
    float* out = (float*)d_out;

    const int B   = in_sizes[1];             // offsets count = batch
    const int bag = in_sizes[0] / B;         // uniform bag size (30)

    const int grid = (B + P - 1) / P;
    nnue_fused_kernel<<<grid, 256>>>(wi, bi, ftw, ftb,
                                     fc1w, fc1b, fc2w, fc2b, fc3w, fc3b,
                                     out, bag, B);
}

// round 6
// speedup vs baseline: 1.5234x; 1.5234x over previous
#include <cuda_runtime.h>
#include <cuda_bf16.h>
#include <cstdint>

// HalfKP NNUE forward, fully fused, 4 positions per block.
// 0 white_indices int32 [B*BAG]   1 white_offsets int64 [B] (unused)
// 2 black_indices int32 [B*BAG]   3 black_offsets int64 [B] (unused)
// 4 ft_white f32 [NUM_EMB,256]    5 ft_black f32 [NUM_EMB,256]
// 6 fc1_w f32 [32,512]  7 fc1_b [32]
// 8 fc2_w f32 [32,32]   9 fc2_b [32]
// 10 fc3_w f32 [1,32]  11 fc3_b [1]
// output f32 [B]

#define H1 256
#define P  4
#define MAXBAG 64

template<int BAG>
__global__ __launch_bounds__(256, 4)
void nnue_fused_kernel(const int* __restrict__ wi,
                       const int* __restrict__ bi,
                       const float* __restrict__ ftw,
                       const float* __restrict__ ftb,
                       const float* __restrict__ fc1w,
                       const float* __restrict__ fc1b,
                       const float* __restrict__ fc2w,
                       const float* __restrict__ fc2b,
                       const float* __restrict__ fc3w,
                       const float* __restrict__ fc3b,
                       float* __restrict__ out,
                       int bagRT, int B)
{
    const int bag = (BAG > 0) ? BAG : bagRT;
    const int t = threadIdx.x;               // 0..255
    const int pos0 = blockIdx.x * P;

    __shared__ int   sW[P][MAXBAG];
    __shared__ int   sB[P][MAXBAG];
    __shared__ float x[P][2 * H1];
    __shared__ float h1[P][32];

    // ---- stage indices ----
    for (int i = t; i < P * bag; i += 256) {
        const int p = i / bag, k = i - p * bag;
        if (pos0 + p < B) {
            const size_t g = (size_t)(pos0 + p) * bag + k;
            sW[p][k] = wi[g];
            sB[p][k] = bi[g];
        } else {
            sW[p][k] = 0;
            sB[p][k] = 0;
        }
    }
    __syncthreads();

    // ---- gather: 64 threads per position; thread owns float4 column c4 of
    //      BOTH tables; fully unrolled bag loop -> deep load batching ----
    {
        const int p  = t >> 6;               // 0..3
        const int c4 = t & 63;               // 0..63
        const float* tw = ftw + (size_t)c4 * 4;
        const float* tb = ftb + (size_t)c4 * 4;

        float4 aw = make_float4(0.f, 0.f, 0.f, 0.f);
        float4 ab = make_float4(0.f, 0.f, 0.f, 0.f);
        #pragma unroll
        for (int k = 0; k < bag; k++) {
            const float4 vw = *reinterpret_cast<const float4*>(tw + (size_t)sW[p][k] * H1);
            const float4 vb = *reinterpret_cast<const float4*>(tb + (size_t)sB[p][k] * H1);
            aw.x += vw.x; aw.y += vw.y; aw.z += vw.z; aw.w += vw.w;
            ab.x += vb.x; ab.y += vb.y; ab.z += vb.z; ab.w += vb.w;
        }
        reinterpret_cast<float4*>(&x[p][0])[c4] =
            make_float4(fmaxf(aw.x, 0.f), fmaxf(aw.y, 0.f),
                        fmaxf(aw.z, 0.f), fmaxf(aw.w, 0.f));
        reinterpret_cast<float4*>(&x[p][H1])[c4] =
            make_float4(fmaxf(ab.x, 0.f), fmaxf(ab.y, 0.f),
                        fmaxf(ab.z, 0.f), fmaxf(ab.w, 0.f));
    }
    __syncthreads();

    // ---- fc1: ALL 256 threads. og = group of 4 outputs (0..7),
    //      l = k-lane (0..31). Weights read once per block. ----
    {
        const int og = t >> 5;               // 0..7
        const int l  = t & 31;               // 0..31
        const float4* w4 = reinterpret_cast<const float4*>(fc1w);

        float acc[P][4];
        #pragma unroll
        for (int p = 0; p < P; p++)
            #pragma unroll
            for (int o = 0; o < 4; o++) acc[p][o] = 0.f;

        #pragma unroll
        for (int j = 0; j < 4; j++) {
            const int k = j * 32 + l;        // float4 index 0..127
            const float4 w0 = w4[(og * 4 + 0) * 128 + k];
            const float4 w1 = w4[(og * 4 + 1) * 128 + k];
            const float4 w2 = w4[(og * 4 + 2) * 128 + k];
            const float4 w3 = w4[(og * 4 + 3) * 128 + k];
            #pragma unroll
            for (int p = 0; p < P; p++) {
                const float4 xv = reinterpret_cast<const float4*>(&x[p][0])[k];
                acc[p][0] += xv.x * w0.x + xv.y * w0.y + xv.z * w0.z + xv.w * w0.w;
                acc[p][1] += xv.x * w1.x + xv.y * w1.y + xv.z * w1.z + xv.w * w1.w;
                acc[p][2] += xv.x * w2.x + xv.y * w2.y + xv.z * w2.z + xv.w * w2.w;
                acc[p][3] += xv.x * w3.x + xv.y * w3.y + xv.z * w3.z + xv.w * w3.w;
            }
        }
        #pragma unroll
        for (int p = 0; p < P; p++)
            #pragma unroll
            for (int o = 0; o < 4; o++) {
                float s = acc[p][o];
                s += __shfl_down_sync(0xffffffffu, s, 16);
                s += __shfl_down_sync(0xffffffffu, s, 8);
                s += __shfl_down_sync(0xffffffffu, s, 4);
                s += __shfl_down_sync(0xffffffffu, s, 2);
                s += __shfl_down_sync(0xffffffffu, s, 1);
                if (l == 0)
                    h1[p][og * 4 + o] = fmaxf(s + fc1b[og * 4 + o], 0.f);
            }
    }
    __syncthreads();

    // ---- fc2 + fc3: one warp per position (4 warps) ----
    if (t < 32 * P) {
        const int p = t >> 5;
        const int o = t & 31;
        float s2 = 0.f;
        #pragma unroll
        for (int k = 0; k < 32; k++) s2 += h1[p][k] * fc2w[o * 32 + k];
        const float h2 = fmaxf(s2 + fc2b[o], 0.f);
        float v = h2 * fc3w[o];
        #pragma unroll
        for (int off = 16; off > 0; off >>= 1)
            v += __shfl_down_sync(0xffffffffu, v, off);
        if (o == 0 && pos0 + p < B) out[pos0 + p] = v + fc3b[0];
    }
}

extern "C" void kernel_launch(void* const* d_in, const int* in_sizes, int n_in,
                              void* d_out, int out_size)
{
    const int*   wi   = (const int*)  d_in[0];
    const int*   bi   = (const int*)  d_in[2];
    const float* ftw  = (const float*)d_in[4];
    const float* ftb  = (const float*)d_in[5];
    const float* fc1w = (const float*)d_in[6];
    const float* fc1b = (const float*)d_in[7];
    const float* fc2w = (const float*)d_in[8];
    const float* fc2b = (const float*)d_in[9];
    const float* fc3w = (const float*)d_in[10];
    const float* fc3b = (const float*)d_in[11];
    float* out = (float*)d_out;

    const int B   = in_sizes[1];
    const int bag = in_sizes[0] / B;          // 30

    const int grid = (B + P - 1) / P;
    if (bag == 30) {
        nnue_fused_kernel<30><<<grid, 256>>>(wi, bi, ftw, ftb,
                                             fc1w, fc1b, fc2w, fc2b, fc3w, fc3b,
                                             out, bag, B);
    } else {
        nnue_fused_kernel<0><<<grid, 256>>>(wi, bi, ftw, ftb,
                                            fc1w, fc1b, fc2w, fc2b, fc3w, fc3b,
                                            out, bag, B);
    }
}

// round 7
// speedup vs baseline: 1.5932x; 1.0458x over previous
#include <cuda_runtime.h>
#include <cuda_fp16.h>
#include <cuda_bf16.h>
#include <cstdint>

// HalfKP NNUE forward. Two-kernel graph:
//  1) convert_tables: fp32 embedding tables -> fp16 __device__ scratch (42MB, L2-resident)
//  2) nnue_fused:     fp16 gather + fp32 MLP, 4 positions per block
//
// Inputs (metadata order):
//  0 white_indices int32 [B*BAG]   1 white_offsets int64 [B] (unused)
//  2 black_indices int32 [B*BAG]   3 black_offsets int64 [B] (unused)
//  4 ft_white f32 [NUM_EMB,256]    5 ft_black f32 [NUM_EMB,256]
//  6 fc1_w f32 [32,512]  7 fc1_b [32]
//  8 fc2_w f32 [32,32]   9 fc2_b [32]
// 10 fc3_w f32 [1,32]   11 fc3_b [1]
// output f32 [B]

#define H1 256
#define P  4
#define MAXBAG 64
#define MAX_EMB 41025
#define TBL_ELEMS (MAX_EMB * H1)   // 10,502,400

__device__ __half g_ftw16[TBL_ELEMS];
__device__ __half g_ftb16[TBL_ELEMS];

// ---- table conversion: 8 floats -> 8 halves per thread ----
__global__ __launch_bounds__(256)
void convert_tables(const float4* __restrict__ fw,
                    const float4* __restrict__ fb,
                    int total8)                    // groups of 8 elems per table
{
    const int i = blockIdx.x * blockDim.x + threadIdx.x;
    if (i >= 2 * total8) return;
    const float4* src;
    __half* dst;
    int j;
    if (i < total8) { src = fw; dst = g_ftw16; j = i; }
    else            { src = fb; dst = g_ftb16; j = i - total8; }
    const float4 a = src[2 * j];
    const float4 c = src[2 * j + 1];
    __half2 h0 = __floats2half2_rn(a.x, a.y);
    __half2 h1 = __floats2half2_rn(a.z, a.w);
    __half2 h2 = __floats2half2_rn(c.x, c.y);
    __half2 h3 = __floats2half2_rn(c.z, c.w);
    uint4 o;
    o.x = *reinterpret_cast<unsigned*>(&h0);
    o.y = *reinterpret_cast<unsigned*>(&h1);
    o.z = *reinterpret_cast<unsigned*>(&h2);
    o.w = *reinterpret_cast<unsigned*>(&h3);
    *reinterpret_cast<uint4*>(dst + 8 * j) = o;
}

__device__ __forceinline__ void acc8_half(const uint4 v, float* a)
{
    const __half2 h0 = *reinterpret_cast<const __half2*>(&v.x);
    const __half2 h1 = *reinterpret_cast<const __half2*>(&v.y);
    const __half2 h2 = *reinterpret_cast<const __half2*>(&v.z);
    const __half2 h3 = *reinterpret_cast<const __half2*>(&v.w);
    const float2 f0 = __half22float2(h0);
    const float2 f1 = __half22float2(h1);
    const float2 f2 = __half22float2(h2);
    const float2 f3 = __half22float2(h3);
    a[0] += f0.x; a[1] += f0.y; a[2] += f1.x; a[3] += f1.y;
    a[4] += f2.x; a[5] += f2.y; a[6] += f3.x; a[7] += f3.y;
}

template<int BAG>
__global__ __launch_bounds__(256, 4)
void nnue_fused_kernel(const int* __restrict__ wi,
                       const int* __restrict__ bi,
                       const float* __restrict__ fc1w,
                       const float* __restrict__ fc1b,
                       const float* __restrict__ fc2w,
                       const float* __restrict__ fc2b,
                       const float* __restrict__ fc3w,
                       const float* __restrict__ fc3b,
                       float* __restrict__ out,
                       int bagRT, int B)
{
    const int bag = (BAG > 0) ? BAG : bagRT;
    const int t = threadIdx.x;               // 0..255
    const int pos0 = blockIdx.x * P;

    __shared__ int   sIdx[2][P][MAXBAG];     // [table][pos][k]
    __shared__ float x[P][2 * H1];
    __shared__ float h1[P][32];

    // ---- stage indices ----
    for (int i = t; i < P * bag; i += 256) {
        const int p = i / bag, k = i - p * bag;
        if (pos0 + p < B) {
            const size_t g = (size_t)(pos0 + p) * bag + k;
            sIdx[0][p][k] = wi[g];
            sIdx[1][p][k] = bi[g];
        } else {
            sIdx[0][p][k] = 0;
            sIdx[1][p][k] = 0;
        }
    }
    __syncthreads();

    // ---- gather (fp16 tables): one warp per (position, table).
    //      Each thread owns 8 columns (16B), 30 fully-unrolled LDG.128. ----
    {
        const int p    = t >> 6;             // 0..3
        const int half = (t >> 5) & 1;       // 0 = white, 1 = black
        const int c8   = t & 31;             // 0..31 (8-col chunk)
        const __half* table = half ? g_ftb16 : g_ftw16;
        const int* idx = sIdx[half][p];
        const __half* base = table + c8 * 8;

        float a[8];
        #pragma unroll
        for (int i = 0; i < 8; i++) a[i] = 0.f;

        #pragma unroll
        for (int k = 0; k < bag; k++) {
            const uint4 v = *reinterpret_cast<const uint4*>(base + (size_t)idx[k] * H1);
            acc8_half(v, a);
        }

        float* xp = &x[p][half * H1 + c8 * 8];
        reinterpret_cast<float4*>(xp)[0] =
            make_float4(fmaxf(a[0], 0.f), fmaxf(a[1], 0.f),
                        fmaxf(a[2], 0.f), fmaxf(a[3], 0.f));
        reinterpret_cast<float4*>(xp)[1] =
            make_float4(fmaxf(a[4], 0.f), fmaxf(a[5], 0.f),
                        fmaxf(a[6], 0.f), fmaxf(a[7], 0.f));
    }
    __syncthreads();

    // ---- fc1: all 256 threads. og = group of 4 outputs (0..7), l = k-lane. ----
    {
        const int og = t >> 5;               // 0..7
        const int l  = t & 31;               // 0..31
        const float4* w4 = reinterpret_cast<const float4*>(fc1w);

        float acc[P][4];
        #pragma unroll
        for (int p = 0; p < P; p++)
            #pragma unroll
            for (int o = 0; o < 4; o++) acc[p][o] = 0.f;

        #pragma unroll
        for (int j = 0; j < 4; j++) {
            const int k = j * 32 + l;        // float4 index 0..127
            const float4 w0 = w4[(og * 4 + 0) * 128 + k];
            const float4 w1 = w4[(og * 4 + 1) * 128 + k];
            const float4 w2 = w4[(og * 4 + 2) * 128 + k];
            const float4 w3 = w4[(og * 4 + 3) * 128 + k];
            #pragma unroll
            for (int p = 0; p < P; p++) {
                const float4 xv = reinterpret_cast<const float4*>(&x[p][0])[k];
                acc[p][0] += xv.x * w0.x + xv.y * w0.y + xv.z * w0.z + xv.w * w0.w;
                acc[p][1] += xv.x * w1.x + xv.y * w1.y + xv.z * w1.z + xv.w * w1.w;
                acc[p][2] += xv.x * w2.x + xv.y * w2.y + xv.z * w2.z + xv.w * w2.w;
                acc[p][3] += xv.x * w3.x + xv.y * w3.y + xv.z * w3.z + xv.w * w3.w;
            }
        }
        #pragma unroll
        for (int p = 0; p < P; p++)
            #pragma unroll
            for (int o = 0; o < 4; o++) {
                float s = acc[p][o];
                s += __shfl_down_sync(0xffffffffu, s, 16);
                s += __shfl_down_sync(0xffffffffu, s, 8);
                s += __shfl_down_sync(0xffffffffu, s, 4);
                s += __shfl_down_sync(0xffffffffu, s, 2);
                s += __shfl_down_sync(0xffffffffu, s, 1);
                if (l == 0)
                    h1[p][og * 4 + o] = fmaxf(s + fc1b[og * 4 + o], 0.f);
            }
    }
    __syncthreads();

    // ---- fc2 + fc3: one warp per position ----
    if (t < 32 * P) {
        const int p = t >> 5;
        const int o = t & 31;
        float s2 = 0.f;
        #pragma unroll
        for (int k = 0; k < 32; k++) s2 += h1[p][k] * fc2w[o * 32 + k];
        const float h2 = fmaxf(s2 + fc2b[o], 0.f);
        float v = h2 * fc3w[o];
        #pragma unroll
        for (int off = 16; off > 0; off >>= 1)
            v += __shfl_down_sync(0xffffffffu, v, off);
        if (o == 0 && pos0 + p < B) out[pos0 + p] = v + fc3b[0];
    }
}

// ---- fallback: fp32 gather (used only if tables exceed static scratch) ----
__global__ __launch_bounds__(256, 4)
void nnue_fused_f32(const int* __restrict__ wi, const int* __restrict__ bi,
                    const float* __restrict__ ftw, const float* __restrict__ ftb,
                    const float* __restrict__ fc1w, const float* __restrict__ fc1b,
                    const float* __restrict__ fc2w, const float* __restrict__ fc2b,
                    const float* __restrict__ fc3w, const float* __restrict__ fc3b,
                    float* __restrict__ out, int bag, int B)
{
    const int t = threadIdx.x;
    const int pos0 = blockIdx.x * P;
    __shared__ int   sW[P][MAXBAG];
    __shared__ int   sB[P][MAXBAG];
    __shared__ float x[P][2 * H1];
    __shared__ float h1[P][32];

    for (int i = t; i < P * bag; i += 256) {
        const int p = i / bag, k = i - p * bag;
        if (pos0 + p < B) {
            const size_t g = (size_t)(pos0 + p) * bag + k;
            sW[p][k] = wi[g]; sB[p][k] = bi[g];
        } else { sW[p][k] = 0; sB[p][k] = 0; }
    }
    __syncthreads();
    {
        const int p  = t >> 6;
        const int c4 = t & 63;
        const float* tw = ftw + (size_t)c4 * 4;
        const float* tb = ftb + (size_t)c4 * 4;
        float4 aw = make_float4(0,0,0,0), ab = make_float4(0,0,0,0);
        for (int k = 0; k < bag; k++) {
            const float4 vw = *reinterpret_cast<const float4*>(tw + (size_t)sW[p][k] * H1);
            const float4 vb = *reinterpret_cast<const float4*>(tb + (size_t)sB[p][k] * H1);
            aw.x += vw.x; aw.y += vw.y; aw.z += vw.z; aw.w += vw.w;
            ab.x += vb.x; ab.y += vb.y; ab.z += vb.z; ab.w += vb.w;
        }
        reinterpret_cast<float4*>(&x[p][0])[c4]  = make_float4(fmaxf(aw.x,0.f),fmaxf(aw.y,0.f),fmaxf(aw.z,0.f),fmaxf(aw.w,0.f));
        reinterpret_cast<float4*>(&x[p][H1])[c4] = make_float4(fmaxf(ab.x,0.f),fmaxf(ab.y,0.f),fmaxf(ab.z,0.f),fmaxf(ab.w,0.f));
    }
    __syncthreads();
    {
        const int og = t >> 5, l = t & 31;
        const float4* w4 = reinterpret_cast<const float4*>(fc1w);
        float acc[P][4];
        for (int p = 0; p < P; p++) for (int o = 0; o < 4; o++) acc[p][o] = 0.f;
        for (int j = 0; j < 4; j++) {
            const int k = j * 32 + l;
            const float4 w0 = w4[(og*4+0)*128+k], w1 = w4[(og*4+1)*128+k];
            const float4 w2 = w4[(og*4+2)*128+k], w3 = w4[(og*4+3)*128+k];
            for (int p = 0; p < P; p++) {
                const float4 xv = reinterpret_cast<const float4*>(&x[p][0])[k];
                acc[p][0] += xv.x*w0.x+xv.y*w0.y+xv.z*w0.z+xv.w*w0.w;
                acc[p][1] += xv.x*w1.x+xv.y*w1.y+xv.z*w1.z+xv.w*w1.w;
                acc[p][2] += xv.x*w2.x+xv.y*w2.y+xv.z*w2.z+xv.w*w2.w;
                acc[p][3] += xv.x*w3.x+xv.y*w3.y+xv.z*w3.z+xv.w*w3.w;
            }
        }
        for (int p = 0; p < P; p++)
            for (int o = 0; o < 4; o++) {
                float s = acc[p][o];
                s += __shfl_down_sync(0xffffffffu, s, 16);
                s += __shfl_down_sync(0xffffffffu, s, 8);
                s += __shfl_down_sync(0xffffffffu, s, 4);
                s += __shfl_down_sync(0xffffffffu, s, 2);
                s += __shfl_down_sync(0xffffffffu, s, 1);
                if (l == 0) h1[p][og*4+o] = fmaxf(s + fc1b[og*4+o], 0.f);
            }
    }
    __syncthreads();
    if (t < 32 * P) {
        const int p = t >> 5, o = t & 31;
        float s2 = 0.f;
        for (int k = 0; k < 32; k++) s2 += h1[p][k] * fc2w[o*32+k];
        const float h2 = fmaxf(s2 + fc2b[o], 0.f);
        float v = h2 * fc3w[o];
        for (int off = 16; off > 0; off >>= 1) v += __shfl_down_sync(0xffffffffu, v, off);
        if (o == 0 && pos0 + p < B) out[pos0 + p] = v + fc3b[0];
    }
}

extern "C" void kernel_launch(void* const* d_in, const int* in_sizes, int n_in,
                              void* d_out, int out_size)
{
    const int*   wi   = (const int*)  d_in[0];
    const int*   bi   = (const int*)  d_in[2];
    const float* ftw  = (const float*)d_in[4];
    const float* ftb  = (const float*)d_in[5];
    const float* fc1w = (const float*)d_in[6];
    const float* fc1b = (const float*)d_in[7];
    const float* fc2w = (const float*)d_in[8];
    const float* fc2b = (const float*)d_in[9];
    const float* fc3w = (const float*)d_in[10];
    const float* fc3b = (const float*)d_in[11];
    float* out = (float*)d_out;

    const int B   = in_sizes[1];
    const int bag = in_sizes[0] / B;          // 30
    const int tblElems = in_sizes[4];
    const int grid = (B + P - 1) / P;

    if (tblElems <= TBL_ELEMS && in_sizes[5] <= TBL_ELEMS &&
        (tblElems % 8) == 0 && bag <= MAXBAG) {
        const int total8 = tblElems / 8;
        const int cgrid = (2 * total8 + 255) / 256;
        convert_tables<<<cgrid, 256>>>((const float4*)ftw, (const float4*)ftb, total8);
        if (bag == 30) {
            nnue_fused_kernel<30><<<grid, 256>>>(wi, bi,
                fc1w, fc1b, fc2w, fc2b, fc3w, fc3b, out, bag, B);
        } else {
            nnue_fused_kernel<0><<<grid, 256>>>(wi, bi,
                fc1w, fc1b, fc2w, fc2b, fc3w, fc3b, out, bag, B);
        }
    } else {
        nnue_fused_f32<<<grid, 256>>>(wi, bi, ftw, ftb,
            fc1w, fc1b, fc2w, fc2b, fc3w, fc3b, out, bag, B);
    }
}